// round 4
// baseline (speedup 1.0000x reference)
#include <cuda_runtime.h>
#include <cuda_bf16.h>
#include <cstdint>

#define EMBED   1024
#define NHEADS  16
#define HDIM    64
#define NB      4
#define SEQ     2048
#define MTOT    (NB*SEQ)     /* 8192 */
#define KDIM    1024
#define NDIM    1024

// ---------------------------------------------------------------------------
// Scratch (device globals; allocation-free per harness rules).
// ---------------------------------------------------------------------------
__device__ float g_Q[(size_t)NB*NHEADS*SEQ*HDIM];  // [b,h,l,d] fp32
__device__ float g_K[(size_t)NB*NHEADS*SEQ*HDIM];
__device__ float g_V[(size_t)NB*NHEADS*SEQ*HDIM];
__device__ float g_O[(size_t)MTOT*EMBED];          // [b*l, e]

__device__ __nv_bfloat16 g_xhi[(size_t)MTOT*KDIM]; // split x
__device__ __nv_bfloat16 g_xlo[(size_t)MTOT*KDIM];
__device__ __nv_bfloat16 g_ohi[(size_t)MTOT*KDIM]; // split attention output
__device__ __nv_bfloat16 g_olo[(size_t)MTOT*KDIM];
__device__ __nv_bfloat16 g_wthi[(size_t)4*NDIM*KDIM]; // W^T split, [N][K], 4 mats
__device__ __nv_bfloat16 g_wtlo[(size_t)4*NDIM*KDIM];

// ---------------------------------------------------------------------------
// mma.sync helpers (arch-portable PTX; runs on tensor pipe, OK at compute_103)
// ---------------------------------------------------------------------------
__device__ __forceinline__ uint32_t smem_u32(const void* p) {
    uint32_t a;
    asm("{ .reg .u64 t; cvta.to.shared.u64 t, %1; cvt.u32.u64 %0, t; }"
        : "=r"(a) : "l"(p));
    return a;
}

__device__ __forceinline__ void ldsm_x4(uint32_t* r, uint32_t addr) {
    asm volatile("ldmatrix.sync.aligned.m8n8.x4.shared.b16 {%0,%1,%2,%3}, [%4];"
        : "=r"(r[0]), "=r"(r[1]), "=r"(r[2]), "=r"(r[3]) : "r"(addr));
}

__device__ __forceinline__ void mma_bf16(float* c, const uint32_t* a, const uint32_t* b) {
    asm volatile(
        "mma.sync.aligned.m16n8k16.row.col.f32.bf16.bf16.f32 "
        "{%0,%1,%2,%3}, {%4,%5,%6,%7}, {%8,%9}, {%0,%1,%2,%3};"
        : "+f"(c[0]), "+f"(c[1]), "+f"(c[2]), "+f"(c[3])
        : "r"(a[0]), "r"(a[1]), "r"(a[2]), "r"(a[3]), "r"(b[0]), "r"(b[1]));
}

// ---------------------------------------------------------------------------
// Split fp32 -> (bf16 hi, bf16 lo). n4 = count of float4 elements.
// ---------------------------------------------------------------------------
__global__ void __launch_bounds__(256) split_kernel(
    const float* __restrict__ in, __nv_bfloat16* __restrict__ hi,
    __nv_bfloat16* __restrict__ lo, int n4)
{
    int i = blockIdx.x * 256 + threadIdx.x;
    if (i >= n4) return;
    float4 v = ((const float4*)in)[i];
    __nv_bfloat16 h0 = __float2bfloat16(v.x);
    __nv_bfloat16 h1 = __float2bfloat16(v.y);
    __nv_bfloat16 h2 = __float2bfloat16(v.z);
    __nv_bfloat16 h3 = __float2bfloat16(v.w);
    __nv_bfloat16 l0 = __float2bfloat16(v.x - __bfloat162float(h0));
    __nv_bfloat16 l1 = __float2bfloat16(v.y - __bfloat162float(h1));
    __nv_bfloat16 l2 = __float2bfloat16(v.z - __bfloat162float(h2));
    __nv_bfloat16 l3 = __float2bfloat16(v.w - __bfloat162float(h3));
    __nv_bfloat162* hi2 = (__nv_bfloat162*)hi;
    __nv_bfloat162* lo2 = (__nv_bfloat162*)lo;
    hi2[2*i]   = __nv_bfloat162(h0, h1);
    hi2[2*i+1] = __nv_bfloat162(h2, h3);
    lo2[2*i]   = __nv_bfloat162(l0, l1);
    lo2[2*i+1] = __nv_bfloat162(l2, l3);
}

// ---------------------------------------------------------------------------
// Transpose + split: W[K][N] fp32 -> Wt_hi/Wt_lo [N][K] bf16.
// ---------------------------------------------------------------------------
__global__ void __launch_bounds__(256) wsplit_kernel(
    const float* __restrict__ W, __nv_bfloat16* __restrict__ hi,
    __nv_bfloat16* __restrict__ lo)
{
    __shared__ float tile[32][33];
    int tx = threadIdx.x & 31, ty0 = threadIdx.x >> 5;
    int bn = blockIdx.x * 32;   // N
    int bk = blockIdx.y * 32;   // K
#pragma unroll
    for (int i = 0; i < 4; i++) {
        int ty = ty0 + i * 8;
        tile[ty][tx] = W[(size_t)(bk + ty) * NDIM + bn + tx];
    }
    __syncthreads();
#pragma unroll
    for (int i = 0; i < 4; i++) {
        int ty = ty0 + i * 8;
        float v = tile[tx][ty];   // = W[bk+tx][bn+ty]
        __nv_bfloat16 h = __float2bfloat16(v);
        size_t o = (size_t)(bn + ty) * KDIM + bk + tx;
        hi[o] = h;
        lo[o] = __float2bfloat16(v - __bfloat162float(h));
    }
}

// ---------------------------------------------------------------------------
// mma.sync split-bf16 GEMM:
//   C[128x128 tile] = A[M,K] @ Bt[N,K]^T (+bias), fp32 accum in registers.
//   3 MMAs per operand pair per k16 (hi*hi + hi*lo + lo*hi).
// 256 threads = 8 warps in 2(M)x4(N) grid, warp tile 64x32.
// K-chunk 32, double-buffered smem (LDG->regs overlapped with compute).
// Smem rows padded to 80B -> conflict-free ldmatrix.
// mode 0/1/2: remap store into g_Q/g_K/g_V [b,h,l,d]; mode 3: plain to Cout.
// ---------------------------------------------------------------------------
#define ROWB      80                  /* padded row bytes (32 bf16 -> 80B) */
#define MAT_BYTES (128*ROWB)          /* 10240 */
#define STG_BYTES (4*MAT_BYTES)       /* 40960 */
#define GEMM_SMEM (2*STG_BYTES)       /* 81920 */
#define OFF_AHI   0
#define OFF_ALO   MAT_BYTES
#define OFF_BHI   (2*MAT_BYTES)
#define OFF_BLO   (3*MAT_BYTES)

__global__ void __launch_bounds__(256, 1) gemm_mma(
    const __nv_bfloat16* __restrict__ Ahi, const __nv_bfloat16* __restrict__ Alo,
    const __nv_bfloat16* __restrict__ Bhi, const __nv_bfloat16* __restrict__ Blo,
    const float* __restrict__ bias, float* __restrict__ Cout, int mode)
{
    extern __shared__ char sm[];
    const uint32_t sb = smem_u32(sm);
    const int t = threadIdx.x;
    const int lane = t & 31;
    const int wid = t >> 5;
    const int wm = wid >> 2;          // 0..1
    const int wn = wid & 3;           // 0..3
    const int bm = blockIdx.y * 128;
    const int bn = blockIdx.x * 128;

    // staging indices (each thread: 2 uint4 per matrix per stage)
    const int r0s = t >> 2,            seg0 = t & 3;
    const int r1s = (t + 256) >> 2,    seg1 = (t + 256) & 3;

    // ldmatrix lane addressing
    const int a_row  = lane & 15;
    const int a_half = lane >> 4;
    const int b_row  = ((lane >> 4) << 3) + (lane & 7);
    const int b_half = (lane >> 3) & 1;

    float acc[16][4];
#pragma unroll
    for (int i = 0; i < 16; i++)
#pragma unroll
        for (int j = 0; j < 4; j++) acc[i][j] = 0.f;

    const size_t a0g = (size_t)(bm + r0s) * KDIM + seg0 * 8;
    const size_t a1g = (size_t)(bm + r1s) * KDIM + seg1 * 8;
    const size_t b0g = (size_t)(bn + r0s) * KDIM + seg0 * 8;
    const size_t b1g = (size_t)(bn + r1s) * KDIM + seg1 * 8;
    const uint32_t s0 = (uint32_t)(r0s * ROWB + seg0 * 16);
    const uint32_t s1 = (uint32_t)(r1s * ROWB + seg1 * 16);

    // prologue: stage 0
    {
        uint4 vah0 = *(const uint4*)(Ahi + a0g);
        uint4 vah1 = *(const uint4*)(Ahi + a1g);
        uint4 val0 = *(const uint4*)(Alo + a0g);
        uint4 val1 = *(const uint4*)(Alo + a1g);
        uint4 vbh0 = *(const uint4*)(Bhi + b0g);
        uint4 vbh1 = *(const uint4*)(Bhi + b1g);
        uint4 vbl0 = *(const uint4*)(Blo + b0g);
        uint4 vbl1 = *(const uint4*)(Blo + b1g);
        *(uint4*)(sm + OFF_AHI + s0) = vah0;
        *(uint4*)(sm + OFF_AHI + s1) = vah1;
        *(uint4*)(sm + OFF_ALO + s0) = val0;
        *(uint4*)(sm + OFF_ALO + s1) = val1;
        *(uint4*)(sm + OFF_BHI + s0) = vbh0;
        *(uint4*)(sm + OFF_BHI + s1) = vbh1;
        *(uint4*)(sm + OFF_BLO + s0) = vbl0;
        *(uint4*)(sm + OFF_BLO + s1) = vbl1;
    }
    __syncthreads();

    const int NSTG = KDIM / 32;       // 32
    for (int s = 0; s < NSTG; s++) {
        // issue next-stage global loads
        uint4 vah0, vah1, val0, val1, vbh0, vbh1, vbl0, vbl1;
        if (s + 1 < NSTG) {
            int k0 = (s + 1) * 32;
            vah0 = *(const uint4*)(Ahi + a0g + k0);
            vah1 = *(const uint4*)(Ahi + a1g + k0);
            val0 = *(const uint4*)(Alo + a0g + k0);
            val1 = *(const uint4*)(Alo + a1g + k0);
            vbh0 = *(const uint4*)(Bhi + b0g + k0);
            vbh1 = *(const uint4*)(Bhi + b1g + k0);
            vbl0 = *(const uint4*)(Blo + b0g + k0);
            vbl1 = *(const uint4*)(Blo + b1g + k0);
        }

        // compute current stage
        const uint32_t stg = sb + (uint32_t)((s & 1) * STG_BYTES);
        const uint32_t aAhi = stg + OFF_AHI + (uint32_t)((wm * 64 + a_row) * ROWB + a_half * 16);
        const uint32_t aAlo = aAhi + MAT_BYTES;
        const uint32_t aBhi = stg + OFF_BHI + (uint32_t)((wn * 32 + b_row) * ROWB + b_half * 16);
        const uint32_t aBlo = aBhi + MAT_BYTES;

#pragma unroll
        for (int kk = 0; kk < 2; kk++) {
            uint32_t ah[4][4], al[4][4], bh[2][4], bl[2][4];
            const uint32_t koff = (uint32_t)(kk * 32);
#pragma unroll
            for (int mt = 0; mt < 4; mt++) {
                ldsm_x4(ah[mt], aAhi + mt * (16 * ROWB) + koff);
                ldsm_x4(al[mt], aAlo + mt * (16 * ROWB) + koff);
            }
#pragma unroll
            for (int nt = 0; nt < 2; nt++) {
                ldsm_x4(bh[nt], aBhi + nt * (16 * ROWB) + koff);
                ldsm_x4(bl[nt], aBlo + nt * (16 * ROWB) + koff);
            }
#pragma unroll
            for (int mt = 0; mt < 4; mt++) {
#pragma unroll
                for (int j = 0; j < 4; j++) {
                    const uint32_t* bhf = &bh[j >> 1][(j & 1) * 2];
                    const uint32_t* blf = &bl[j >> 1][(j & 1) * 2];
                    float* c = acc[mt * 4 + j];
                    mma_bf16(c, ah[mt], bhf);
                    mma_bf16(c, ah[mt], blf);
                    mma_bf16(c, al[mt], bhf);
                }
            }
        }

        // store next stage and sync
        if (s + 1 < NSTG) {
            char* dst = sm + ((s + 1) & 1) * STG_BYTES;
            *(uint4*)(dst + OFF_AHI + s0) = vah0;
            *(uint4*)(dst + OFF_AHI + s1) = vah1;
            *(uint4*)(dst + OFF_ALO + s0) = val0;
            *(uint4*)(dst + OFF_ALO + s1) = val1;
            *(uint4*)(dst + OFF_BHI + s0) = vbh0;
            *(uint4*)(dst + OFF_BHI + s1) = vbh1;
            *(uint4*)(dst + OFF_BLO + s0) = vbl0;
            *(uint4*)(dst + OFF_BLO + s1) = vbl1;
            __syncthreads();
        }
    }

    // epilogue
    float* dst = (mode == 0) ? g_Q : (mode == 1) ? g_K : (mode == 2) ? g_V : Cout;
    const int g = lane >> 2;
    const int cq = (lane & 3) * 2;
#pragma unroll
    for (int mt = 0; mt < 4; mt++) {
#pragma unroll
        for (int j = 0; j < 4; j++) {
            const float* c = acc[mt * 4 + j];
            int row = bm + wm * 64 + mt * 16 + g;
            int col = bn + wn * 32 + j * 8 + cq;
            float b0 = bias[col], b1 = bias[col + 1];
#pragma unroll
            for (int half = 0; half < 2; half++) {
                int r = row + half * 8;
                float2 v = make_float2(c[half * 2 + 0] + b0, c[half * 2 + 1] + b1);
                if (mode <= 2) {
                    int b_ = r >> 11, l = r & (SEQ - 1);
                    int h = col >> 6, d = col & 63;
                    *(float2*)&dst[((((size_t)b_ * NHEADS + h) * SEQ) + l) * HDIM + d] = v;
                } else {
                    *(float2*)&dst[(size_t)r * NDIM + col] = v;
                }
            }
        }
    }
}

// ---------------------------------------------------------------------------
// Flash attention (fp32 SIMT, unchanged — round-4 target)
// ---------------------------------------------------------------------------
#define ATT_SMEM_FLOATS (64*64 + 3*64*65)

__global__ void __launch_bounds__(256) attn_kernel(const int* __restrict__ mask)
{
    extern __shared__ float smf[];
    float* Qs = smf;               // [64][64]
    float* Ks = Qs + 64*64;        // [64][65]
    float* Vs = Ks + 64*65;        // [64][65]
    float* Ps = Vs + 64*65;        // [64][65]

    int t  = threadIdx.x;
    int bh = blockIdx.y;
    int b  = bh >> 4;
    int qbase = blockIdx.x * 64;

    const float* Qp = g_Q + (size_t)bh * SEQ * HDIM + (size_t)qbase * HDIM;
    const float* Kp = g_K + (size_t)bh * SEQ * HDIM;
    const float* Vp = g_V + (size_t)bh * SEQ * HDIM;
    const int* mrow = mask + (size_t)b * SEQ * SEQ;
    int h = bh & 15;

    int rg = t >> 4, cg = t & 15;
    int r0 = rg * 4, c0 = cg * 4;

    for (int f = t; f < 1024; f += 256)
        ((float4*)Qs)[f] = ((const float4*)Qp)[f];

    float m_i[4], l_i[4], acc[4][4];
#pragma unroll
    for (int i = 0; i < 4; i++) {
        m_i[i] = -1e30f; l_i[i] = 0.f;
#pragma unroll
        for (int j = 0; j < 4; j++) acc[i][j] = 0.f;
    }
    __syncthreads();

    for (int kt = 0; kt < SEQ/64; kt++) {
        int kbase = kt * 64;
        const float4* kg = (const float4*)(Kp + (size_t)kbase * HDIM);
        const float4* vg = (const float4*)(Vp + (size_t)kbase * HDIM);
        for (int f = t; f < 1024; f += 256) {
            int row = f >> 4, col = (f & 15) * 4;
            float4 kv = kg[f];
            float4 vv = vg[f];
            float* kd = &Ks[row*65 + col];
            kd[0]=kv.x; kd[1]=kv.y; kd[2]=kv.z; kd[3]=kv.w;
            float* vd = &Vs[row*65 + col];
            vd[0]=vv.x; vd[1]=vv.y; vd[2]=vv.z; vd[3]=vv.w;
        }
        __syncthreads();

        float s[4][4];
#pragma unroll
        for (int i = 0; i < 4; i++)
#pragma unroll
            for (int j = 0; j < 4; j++) s[i][j] = 0.f;

#pragma unroll 4
        for (int d = 0; d < 64; d++) {
            float qv[4], kv[4];
#pragma unroll
            for (int i = 0; i < 4; i++) qv[i] = Qs[(r0+i)*64 + d];
#pragma unroll
            for (int j = 0; j < 4; j++) kv[j] = Ks[(c0+j)*65 + d];
#pragma unroll
            for (int i = 0; i < 4; i++)
#pragma unroll
                for (int j = 0; j < 4; j++)
                    s[i][j] += qv[i] * kv[j];
        }

#pragma unroll
        for (int i = 0; i < 4; i++) {
            const int4 mk = *(const int4*)&mrow[(size_t)(qbase+r0+i)*SEQ + kbase + c0];
            float sv[4];
            sv[0] = ((mk.x == 0) ? -1e20f : s[i][0]) * 0.125f;
            sv[1] = ((mk.y == 0) ? -1e20f : s[i][1]) * 0.125f;
            sv[2] = ((mk.z == 0) ? -1e20f : s[i][2]) * 0.125f;
            sv[3] = ((mk.w == 0) ? -1e20f : s[i][3]) * 0.125f;

            float mx = fmaxf(fmaxf(sv[0], sv[1]), fmaxf(sv[2], sv[3]));
            mx = fmaxf(mx, __shfl_xor_sync(0xffffffffu, mx, 8));
            mx = fmaxf(mx, __shfl_xor_sync(0xffffffffu, mx, 4));
            mx = fmaxf(mx, __shfl_xor_sync(0xffffffffu, mx, 2));
            mx = fmaxf(mx, __shfl_xor_sync(0xffffffffu, mx, 1));

            float nm = fmaxf(m_i[i], mx);
            float corr = __expf(m_i[i] - nm);

            float p0 = __expf(sv[0] - nm);
            float p1 = __expf(sv[1] - nm);
            float p2 = __expf(sv[2] - nm);
            float p3 = __expf(sv[3] - nm);
            float* pr = &Ps[(r0+i)*65 + c0];
            pr[0] = p0; pr[1] = p1; pr[2] = p2; pr[3] = p3;

            float ls = p0 + p1 + p2 + p3;
            ls += __shfl_xor_sync(0xffffffffu, ls, 8);
            ls += __shfl_xor_sync(0xffffffffu, ls, 4);
            ls += __shfl_xor_sync(0xffffffffu, ls, 2);
            ls += __shfl_xor_sync(0xffffffffu, ls, 1);

            l_i[i] = l_i[i] * corr + ls;
            m_i[i] = nm;
#pragma unroll
            for (int j = 0; j < 4; j++) acc[i][j] *= corr;
        }
        __syncthreads();

#pragma unroll 4
        for (int k = 0; k < 64; k++) {
            float pv[4], vv[4];
#pragma unroll
            for (int i = 0; i < 4; i++) pv[i] = Ps[(r0+i)*65 + k];
#pragma unroll
            for (int j = 0; j < 4; j++) vv[j] = Vs[k*65 + c0 + j];
#pragma unroll
            for (int i = 0; i < 4; i++)
#pragma unroll
                for (int j = 0; j < 4; j++)
                    acc[i][j] += pv[i] * vv[j];
        }
        __syncthreads();
    }

#pragma unroll
    for (int i = 0; i < 4; i++) {
        float inv = 1.f / l_i[i];
        int q = qbase + r0 + i;
        float* op = &g_O[(size_t)(b*SEQ + q)*EMBED + h*HDIM + c0];
#pragma unroll
        for (int j = 0; j < 4; j++) op[j] = acc[i][j] * inv;
    }
}

// ---------------------------------------------------------------------------
extern "C" void kernel_launch(void* const* d_in, const int* in_sizes, int n_in,
                              void* d_out, int out_size)
{
    const float* x    = (const float*)d_in[0];
    const int*   mask = (const int*)  d_in[1];
    const float* Wq   = (const float*)d_in[2];
    const float* bq   = (const float*)d_in[3];
    const float* Wk   = (const float*)d_in[4];
    const float* bk   = (const float*)d_in[5];
    const float* Wv   = (const float*)d_in[6];
    const float* bv   = (const float*)d_in[7];
    const float* Wo   = (const float*)d_in[8];
    const float* bo   = (const float*)d_in[9];

    // Resolve device-global scratch addresses
    __nv_bfloat16 *xhi, *xlo, *ohi, *olo, *wthi, *wtlo;
    float *oO;
    cudaGetSymbolAddress((void**)&xhi,  g_xhi);
    cudaGetSymbolAddress((void**)&xlo,  g_xlo);
    cudaGetSymbolAddress((void**)&ohi,  g_ohi);
    cudaGetSymbolAddress((void**)&olo,  g_olo);
    cudaGetSymbolAddress((void**)&wthi, g_wthi);
    cudaGetSymbolAddress((void**)&wtlo, g_wtlo);
    cudaGetSymbolAddress((void**)&oO,   g_O);

    const size_t WSZ = (size_t)NDIM * KDIM;

    // Split x into bf16 hi/lo
    int n4x = MTOT * KDIM / 4;
    split_kernel<<<(n4x + 255) / 256, 256>>>(x, xhi, xlo, n4x);

    // Transpose+split all four weight matrices
    dim3 wg(NDIM / 32, KDIM / 32);
    wsplit_kernel<<<wg, 256>>>(Wq, wthi + 0 * WSZ, wtlo + 0 * WSZ);
    wsplit_kernel<<<wg, 256>>>(Wk, wthi + 1 * WSZ, wtlo + 1 * WSZ);
    wsplit_kernel<<<wg, 256>>>(Wv, wthi + 2 * WSZ, wtlo + 2 * WSZ);
    wsplit_kernel<<<wg, 256>>>(Wo, wthi + 3 * WSZ, wtlo + 3 * WSZ);

    cudaFuncSetAttribute(gemm_mma, cudaFuncAttributeMaxDynamicSharedMemorySize, GEMM_SMEM);
    dim3 gg(NDIM / 128, MTOT / 128);   // (8, 64)

    gemm_mma<<<gg, 256, GEMM_SMEM>>>(xhi, xlo, wthi + 0 * WSZ, wtlo + 0 * WSZ, bq, nullptr, 0);
    gemm_mma<<<gg, 256, GEMM_SMEM>>>(xhi, xlo, wthi + 1 * WSZ, wtlo + 1 * WSZ, bk, nullptr, 1);
    gemm_mma<<<gg, 256, GEMM_SMEM>>>(xhi, xlo, wthi + 2 * WSZ, wtlo + 2 * WSZ, bv, nullptr, 2);

    int smem = ATT_SMEM_FLOATS * (int)sizeof(float);
    cudaFuncSetAttribute(attn_kernel, cudaFuncAttributeMaxDynamicSharedMemorySize, smem);
    dim3 ga(SEQ / 64, NB * NHEADS);    // (32, 64)
    attn_kernel<<<ga, 256, smem>>>(mask);

    // Split attention output, final projection
    split_kernel<<<(n4x + 255) / 256, 256>>>(oO, ohi, olo, n4x);
    gemm_mma<<<gg, 256, GEMM_SMEM>>>(ohi, olo, wthi + 3 * WSZ, wtlo + 3 * WSZ, bo, (float*)d_out, 3);
}

// round 6
// speedup vs baseline: 2.3971x; 2.3971x over previous
#include <cuda_runtime.h>
#include <cuda_bf16.h>
#include <cuda_fp16.h>
#include <cstdint>

#define EMBED   1024
#define NHEADS  16
#define HDIM    64
#define NB      4
#define SEQ     2048
#define MTOT    (NB*SEQ)
#define KDIM    1024
#define NDIM    1024
#define QSCALE  0.18033688011112042f  /* 0.125 * log2(e) */

// ---- device-global scratch ----
__device__ __half g_qhi[(size_t)NB*NHEADS*SEQ*HDIM];
__device__ __half g_qlo[(size_t)NB*NHEADS*SEQ*HDIM];
__device__ __half g_khi[(size_t)NB*NHEADS*SEQ*HDIM];
__device__ __half g_klo[(size_t)NB*NHEADS*SEQ*HDIM];
__device__ __half g_vhi[(size_t)NB*NHEADS*SEQ*HDIM];
__device__ __half g_vlo[(size_t)NB*NHEADS*SEQ*HDIM];
__device__ float g_O[(size_t)MTOT*EMBED];
__device__ __nv_bfloat16 g_xhi[(size_t)MTOT*KDIM];
__device__ __nv_bfloat16 g_xlo[(size_t)MTOT*KDIM];
__device__ __nv_bfloat16 g_ohi[(size_t)MTOT*EMBED];
__device__ __nv_bfloat16 g_olo[(size_t)MTOT*EMBED];
__device__ __nv_bfloat16 g_wthi[(size_t)4*NDIM*KDIM];
__device__ __nv_bfloat16 g_wtlo[(size_t)4*NDIM*KDIM];
__device__ uint32_t g_mpack[(size_t)NB*SEQ*(SEQ/32)];

// ---- PTX helpers ----
__device__ __forceinline__ uint32_t smem_u32(const void* p) {
    uint32_t a;
    asm("{ .reg .u64 t; cvta.to.shared.u64 t, %1; cvt.u32.u64 %0, t; }" : "=r"(a) : "l"(p));
    return a;
}
__device__ __forceinline__ void ldsm_x4(uint32_t* r, uint32_t addr) {
    asm volatile("ldmatrix.sync.aligned.m8n8.x4.shared.b16 {%0,%1,%2,%3}, [%4];"
        : "=r"(r[0]), "=r"(r[1]), "=r"(r[2]), "=r"(r[3]) : "r"(addr));
}
__device__ __forceinline__ void ldsm_x4_t(uint32_t* r, uint32_t addr) {
    asm volatile("ldmatrix.sync.aligned.m8n8.x4.trans.shared.b16 {%0,%1,%2,%3}, [%4];"
        : "=r"(r[0]), "=r"(r[1]), "=r"(r[2]), "=r"(r[3]) : "r"(addr));
}
__device__ __forceinline__ void mma_bf16(float* c, const uint32_t* a, const uint32_t* b) {
    asm volatile("mma.sync.aligned.m16n8k16.row.col.f32.bf16.bf16.f32 "
        "{%0,%1,%2,%3}, {%4,%5,%6,%7}, {%8,%9}, {%0,%1,%2,%3};"
        : "+f"(c[0]), "+f"(c[1]), "+f"(c[2]), "+f"(c[3])
        : "r"(a[0]), "r"(a[1]), "r"(a[2]), "r"(a[3]), "r"(b[0]), "r"(b[1]));
}
__device__ __forceinline__ void mma_f16(float* c, const uint32_t* a, const uint32_t* b) {
    asm volatile("mma.sync.aligned.m16n8k16.row.col.f32.f16.f16.f32 "
        "{%0,%1,%2,%3}, {%4,%5,%6,%7}, {%8,%9}, {%0,%1,%2,%3};"
        : "+f"(c[0]), "+f"(c[1]), "+f"(c[2]), "+f"(c[3])
        : "r"(a[0]), "r"(a[1]), "r"(a[2]), "r"(a[3]), "r"(b[0]), "r"(b[1]));
}
__device__ __forceinline__ void cp16(uint32_t dst, const void* src) {
    asm volatile("cp.async.cg.shared.global [%0], [%1], 16;"
        :: "r"(dst), "l"(__cvta_generic_to_global(src)));
}
__device__ __forceinline__ float ex2f(float y) {
    float r; asm("ex2.approx.f32 %0, %1;" : "=f"(r) : "f"(y)); return r;
}
__device__ __forceinline__ uint32_t pack_h2(float a, float b) {
    __half2 h = __halves2half2(__float2half_rn(a), __float2half_rn(b));
    return *(uint32_t*)&h;
}

// ---- split fp32 -> bf16 hi/lo ----
__global__ void __launch_bounds__(256) split_kernel(
    const float* __restrict__ in, __nv_bfloat16* __restrict__ hi,
    __nv_bfloat16* __restrict__ lo, int n4)
{
    int i = blockIdx.x * 256 + threadIdx.x;
    if (i >= n4) return;
    float4 v = ((const float4*)in)[i];
    __nv_bfloat16 h0 = __float2bfloat16(v.x), h1 = __float2bfloat16(v.y);
    __nv_bfloat16 h2 = __float2bfloat16(v.z), h3 = __float2bfloat16(v.w);
    ((__nv_bfloat162*)hi)[2*i]   = __nv_bfloat162(h0, h1);
    ((__nv_bfloat162*)hi)[2*i+1] = __nv_bfloat162(h2, h3);
    ((__nv_bfloat162*)lo)[2*i]   = __nv_bfloat162(
        __float2bfloat16(v.x - __bfloat162float(h0)), __float2bfloat16(v.y - __bfloat162float(h1)));
    ((__nv_bfloat162*)lo)[2*i+1] = __nv_bfloat162(
        __float2bfloat16(v.z - __bfloat162float(h2)), __float2bfloat16(v.w - __bfloat162float(h3)));
}

// ---- transpose+split W ----
__global__ void __launch_bounds__(256) wsplit_kernel(
    const float* __restrict__ W, __nv_bfloat16* __restrict__ hi, __nv_bfloat16* __restrict__ lo)
{
    __shared__ float tile[32][33];
    int tx = threadIdx.x & 31, ty0 = threadIdx.x >> 5;
    int bn = blockIdx.x * 32, bk = blockIdx.y * 32;
#pragma unroll
    for (int i = 0; i < 4; i++)
        tile[ty0 + i*8][tx] = W[(size_t)(bk + ty0 + i*8) * NDIM + bn + tx];
    __syncthreads();
#pragma unroll
    for (int i = 0; i < 4; i++) {
        int ty = ty0 + i * 8;
        float v = tile[tx][ty];
        __nv_bfloat16 h = __float2bfloat16(v);
        size_t o = (size_t)(bn + ty) * KDIM + bk + tx;
        hi[o] = h;
        lo[o] = __float2bfloat16(v - __bfloat162float(h));
    }
}

// ---- pack mask to bits ----
__global__ void __launch_bounds__(256) pack_mask(const int* __restrict__ m)
{
    int gw = (blockIdx.x * 256 + threadIdx.x) >> 5;
    int lane = threadIdx.x & 31;
    size_t base = (size_t)gw * 1024;
#pragma unroll 4
    for (int i = 0; i < 32; i++) {
        uint32_t bal = __ballot_sync(0xffffffffu, m[base + i*32 + lane] != 0);
        if (lane == 0) g_mpack[(size_t)gw * 32 + i] = bal;
    }
}

// ---- split-bf16 tensor GEMM (fp16-split epilogue for QKV) ----
#define ROWB      80
#define MAT_BYTES (128*ROWB)
#define STG_BYTES (4*MAT_BYTES)
#define GEMM_SMEM (2*STG_BYTES)
#define OFF_ALO   MAT_BYTES
#define OFF_BHI   (2*MAT_BYTES)
#define OFF_BLO   (3*MAT_BYTES)

__global__ void __launch_bounds__(256, 1) gemm_mma(
    const __nv_bfloat16* __restrict__ Ahi, const __nv_bfloat16* __restrict__ Alo,
    const __nv_bfloat16* __restrict__ Bhi, const __nv_bfloat16* __restrict__ Blo,
    const float* __restrict__ bias, float* __restrict__ Cout, int mode)
{
    extern __shared__ char sm[];
    const uint32_t sb = smem_u32(sm);
    const int t = threadIdx.x, lane = t & 31, wid = t >> 5;
    const int wm = wid >> 2, wn = wid & 3;
    const int bm = blockIdx.y * 128, bn = blockIdx.x * 128;
    const int r0s = t >> 2, seg0 = t & 3;
    const int r1s = (t + 256) >> 2, seg1 = (t + 256) & 3;
    const int a_row = lane & 15, a_half = lane >> 4;
    const int b_row = ((lane >> 4) << 3) + (lane & 7), b_half = (lane >> 3) & 1;

    float acc[16][4];
#pragma unroll
    for (int i = 0; i < 16; i++)
#pragma unroll
        for (int j = 0; j < 4; j++) acc[i][j] = 0.f;

    const size_t a0g = (size_t)(bm + r0s) * KDIM + seg0 * 8;
    const size_t a1g = (size_t)(bm + r1s) * KDIM + seg1 * 8;
    const size_t b0g = (size_t)(bn + r0s) * KDIM + seg0 * 8;
    const size_t b1g = (size_t)(bn + r1s) * KDIM + seg1 * 8;
    const uint32_t s0 = (uint32_t)(r0s * ROWB + seg0 * 16);
    const uint32_t s1 = (uint32_t)(r1s * ROWB + seg1 * 16);

    {
        *(uint4*)(sm + s0) = *(const uint4*)(Ahi + a0g);
        *(uint4*)(sm + s1) = *(const uint4*)(Ahi + a1g);
        *(uint4*)(sm + OFF_ALO + s0) = *(const uint4*)(Alo + a0g);
        *(uint4*)(sm + OFF_ALO + s1) = *(const uint4*)(Alo + a1g);
        *(uint4*)(sm + OFF_BHI + s0) = *(const uint4*)(Bhi + b0g);
        *(uint4*)(sm + OFF_BHI + s1) = *(const uint4*)(Bhi + b1g);
        *(uint4*)(sm + OFF_BLO + s0) = *(const uint4*)(Blo + b0g);
        *(uint4*)(sm + OFF_BLO + s1) = *(const uint4*)(Blo + b1g);
    }
    __syncthreads();

    const int NSTG = KDIM / 32;
    for (int s = 0; s < NSTG; s++) {
        uint4 vah0, vah1, val0, val1, vbh0, vbh1, vbl0, vbl1;
        if (s + 1 < NSTG) {
            int k0 = (s + 1) * 32;
            vah0 = *(const uint4*)(Ahi + a0g + k0); vah1 = *(const uint4*)(Ahi + a1g + k0);
            val0 = *(const uint4*)(Alo + a0g + k0); val1 = *(const uint4*)(Alo + a1g + k0);
            vbh0 = *(const uint4*)(Bhi + b0g + k0); vbh1 = *(const uint4*)(Bhi + b1g + k0);
            vbl0 = *(const uint4*)(Blo + b0g + k0); vbl1 = *(const uint4*)(Blo + b1g + k0);
        }
        const uint32_t stg = sb + (uint32_t)((s & 1) * STG_BYTES);
        const uint32_t aAhi = stg + (uint32_t)((wm * 64 + a_row) * ROWB + a_half * 16);
        const uint32_t aAlo = aAhi + MAT_BYTES;
        const uint32_t aBhi = stg + OFF_BHI + (uint32_t)((wn * 32 + b_row) * ROWB + b_half * 16);
        const uint32_t aBlo = aBhi + MAT_BYTES;
#pragma unroll
        for (int kk = 0; kk < 2; kk++) {
            uint32_t ah[4][4], al[4][4], bh[2][4], bl[2][4];
            const uint32_t koff = (uint32_t)(kk * 32);
#pragma unroll
            for (int mt = 0; mt < 4; mt++) {
                ldsm_x4(ah[mt], aAhi + mt * (16 * ROWB) + koff);
                ldsm_x4(al[mt], aAlo + mt * (16 * ROWB) + koff);
            }
#pragma unroll
            for (int nt = 0; nt < 2; nt++) {
                ldsm_x4(bh[nt], aBhi + nt * (16 * ROWB) + koff);
                ldsm_x4(bl[nt], aBlo + nt * (16 * ROWB) + koff);
            }
#pragma unroll
            for (int mt = 0; mt < 4; mt++)
#pragma unroll
                for (int j = 0; j < 4; j++) {
                    const uint32_t* bhf = &bh[j >> 1][(j & 1) * 2];
                    const uint32_t* blf = &bl[j >> 1][(j & 1) * 2];
                    float* c = acc[mt * 4 + j];
                    mma_bf16(c, ah[mt], bhf);
                    mma_bf16(c, ah[mt], blf);
                    mma_bf16(c, al[mt], bhf);
                }
        }
        if (s + 1 < NSTG) {
            char* dst = sm + ((s + 1) & 1) * STG_BYTES;
            *(uint4*)(dst + s0) = vah0;           *(uint4*)(dst + s1) = vah1;
            *(uint4*)(dst + OFF_ALO + s0) = val0; *(uint4*)(dst + OFF_ALO + s1) = val1;
            *(uint4*)(dst + OFF_BHI + s0) = vbh0; *(uint4*)(dst + OFF_BHI + s1) = vbh1;
            *(uint4*)(dst + OFF_BLO + s0) = vbl0; *(uint4*)(dst + OFF_BLO + s1) = vbl1;
            __syncthreads();
        }
    }

    __half* dsth = (mode == 0) ? g_qhi : (mode == 1) ? g_khi : g_vhi;
    __half* dstl = (mode == 0) ? g_qlo : (mode == 1) ? g_klo : g_vlo;
    const float qs = (mode == 0) ? QSCALE : 1.f;
    const int g = lane >> 2, cq = (lane & 3) * 2;
#pragma unroll
    for (int mt = 0; mt < 4; mt++)
#pragma unroll
        for (int j = 0; j < 4; j++) {
            const float* c = acc[mt * 4 + j];
            int row = bm + wm * 64 + mt * 16 + g;
            int col = bn + wn * 32 + j * 8 + cq;
            float b0 = bias[col], b1 = bias[col + 1];
#pragma unroll
            for (int hf = 0; hf < 2; hf++) {
                int r = row + hf * 8;
                float v0 = c[hf * 2] + b0, v1 = c[hf * 2 + 1] + b1;
                if (mode <= 2) {
                    v0 *= qs; v1 *= qs;
                    __half h0 = __float2half_rn(v0), h1 = __float2half_rn(v1);
                    __half e0 = __float2half_rn(v0 - __half2float(h0));
                    __half e1 = __float2half_rn(v1 - __half2float(h1));
                    int b_ = r >> 11, l = r & (SEQ - 1), hh = col >> 6, d = col & 63;
                    size_t idx = ((((size_t)b_ * NHEADS + hh) * SEQ) + l) * HDIM + d;
                    *(__half2*)&dsth[idx] = __halves2half2(h0, h1);
                    *(__half2*)&dstl[idx] = __halves2half2(e0, e1);
                } else {
                    *(float2*)&Cout[(size_t)r * NDIM + col] = make_float2(v0, v1);
                }
            }
        }
}

// ---- tensor-core flash attention ----
#define AROWB  144
#define KV_MAT (64*AROWB)
#define KV_STG (4*KV_MAT)
#define AQ_OFF (2*KV_STG)
#define AQ_MAT (128*AROWB)
#define ATT_SMEM (AQ_OFF + 2*AQ_MAT)   /* 110592 */

__global__ void __launch_bounds__(256, 1) attn_mma()
{
    extern __shared__ char sm[];
    const uint32_t sb = smem_u32(sm);
    const int t = threadIdx.x, lane = t & 31, wid = t >> 5;
    const int bh = blockIdx.y, b = bh >> 4, h = bh & 15;
    const int qbase = blockIdx.x * 128;

    const __half* Qh = g_qhi + (size_t)bh * SEQ * HDIM + (size_t)qbase * HDIM;
    const __half* Ql = g_qlo + (size_t)bh * SEQ * HDIM + (size_t)qbase * HDIM;
    const __half* Kh = g_khi + (size_t)bh * SEQ * HDIM;
    const __half* Kl = g_klo + (size_t)bh * SEQ * HDIM;
    const __half* Vh = g_vhi + (size_t)bh * SEQ * HDIM;
    const __half* Vl = g_vlo + (size_t)bh * SEQ * HDIM;

    // stage Q (hi/lo) into padded smem
#pragma unroll
    for (int j = 0; j < 8; j++) {
        int mat = j >> 2;
        int r = (t >> 3) + (j & 3) * 32;
        int ch = t & 7;
        const __half* src = (mat ? Ql : Qh) + (size_t)r * 64 + ch * 8;
        *(uint4*)(sm + AQ_OFF + mat * AQ_MAT + r * AROWB + ch * 16) = *(const uint4*)src;
    }
    __syncthreads();

    // Q fragments (16 rows per warp)
    uint32_t qh[4][4], ql[4][4];
    {
        uint32_t aq = sb + AQ_OFF + (uint32_t)((wid * 16 + (lane & 15)) * AROWB + (lane >> 4) * 16);
#pragma unroll
        for (int ks = 0; ks < 4; ks++) {
            ldsm_x4(qh[ks], aq + ks * 32);
            ldsm_x4(ql[ks], aq + AQ_MAT + ks * 32);
        }
    }

    const int b_row = ((lane >> 4) << 3) + (lane & 7), b_half = (lane >> 3) & 1;
    const uint32_t vrow = (uint32_t)((lane & 7) + ((lane >> 4) << 3));
    const uint32_t vcol = (uint32_t)(((lane >> 3) & 1) << 4);

    float oacc[8][4];
#pragma unroll
    for (int i = 0; i < 8; i++)
#pragma unroll
        for (int j = 0; j < 4; j++) oacc[i][j] = 0.f;
    float lsum0 = 0.f, lsum1 = 0.f;

    const int qr0 = qbase + wid * 16 + (lane >> 2);
    const uint32_t* mrow = g_mpack + ((size_t)b * SEQ + qr0) * 64;

    // prologue stage kt=0
#pragma unroll
    for (int j = 0; j < 8; j++) {
        int mat = j >> 1;
        int r = (t >> 3) + (j & 1) * 32;
        int ch = t & 7;
        const __half* src = (mat == 0 ? Kh : mat == 1 ? Kl : mat == 2 ? Vh : Vl) + (size_t)r * 64 + ch * 8;
        cp16(sb + mat * KV_MAT + r * AROWB + ch * 16, src);
    }
    asm volatile("cp.async.commit_group;");

    for (int kt = 0; kt < SEQ / 64; kt++) {
        if (kt + 1 < SEQ / 64) {
            int kb = (kt + 1) * 64;
            uint32_t dstb = sb + ((kt + 1) & 1) * KV_STG;
#pragma unroll
            for (int j = 0; j < 8; j++) {
                int mat = j >> 1;
                int r = (t >> 3) + (j & 1) * 32;
                int ch = t & 7;
                const __half* src = (mat == 0 ? Kh : mat == 1 ? Kl : mat == 2 ? Vh : Vl)
                                    + (size_t)(kb + r) * 64 + ch * 8;
                cp16(dstb + mat * KV_MAT + r * AROWB + ch * 16, src);
            }
            asm volatile("cp.async.commit_group;");
            asm volatile("cp.async.wait_group 1;");
        } else {
            asm volatile("cp.async.wait_group 0;");
        }
        __syncthreads();

        const uint32_t kvb = sb + (kt & 1) * KV_STG;

        // ---- S = Q K^T (3-MMA fp16 split), fp32 accum ----
        float sacc[8][4];
#pragma unroll
        for (int i = 0; i < 8; i++)
#pragma unroll
            for (int j = 0; j < 4; j++) sacc[i][j] = 0.f;

        const uint32_t aKh = kvb + (uint32_t)(b_row * AROWB + b_half * 16);
        const uint32_t aKl = aKh + KV_MAT;
#pragma unroll
        for (int ks = 0; ks < 4; ks++)
#pragma unroll
            for (int nt2 = 0; nt2 < 4; nt2++) {
                uint32_t bh_[4], bl_[4];
                ldsm_x4(bh_, aKh + nt2 * (16 * AROWB) + ks * 32);
                ldsm_x4(bl_, aKl + nt2 * (16 * AROWB) + ks * 32);
#pragma unroll
                for (int j2 = 0; j2 < 2; j2++) {
                    float* c = sacc[nt2 * 2 + j2];
                    mma_f16(c, qh[ks], &bh_[j2 * 2]);
                    mma_f16(c, qh[ks], &bl_[j2 * 2]);
                    mma_f16(c, ql[ks], &bh_[j2 * 2]);
                }
            }

        // ---- mask + 2^y + repack P into A-fragments (in registers) ----
        uint32_t m0a = mrow[kt * 2], m0b = mrow[kt * 2 + 1];
        uint32_t m1a = mrow[512 + kt * 2], m1b = mrow[512 + kt * 2 + 1];
        uint32_t ph[4][4];
#pragma unroll
        for (int nt = 0; nt < 8; nt++) {
            int cb = nt * 8 + (lane & 3) * 2;
            uint32_t w0 = (nt < 4) ? m0a : m0b;
            uint32_t w1 = (nt < 4) ? m1a : m1b;
            int sh = cb & 31;
            float y00 = ((w0 >> sh) & 1) ? sacc[nt][0] : -24.f;
            float y01 = ((w0 >> (sh + 1)) & 1) ? sacc[nt][1] : -24.f;
            float y10 = ((w1 >> sh) & 1) ? sacc[nt][2] : -24.f;
            float y11 = ((w1 >> (sh + 1)) & 1) ? sacc[nt][3] : -24.f;
            float p00 = ex2f(y00), p01 = ex2f(y01), p10 = ex2f(y10), p11 = ex2f(y11);
            lsum0 += p00 + p01;
            lsum1 += p10 + p11;
            ph[nt >> 1][(nt & 1) * 2 + 0] = pack_h2(p00, p01);
            ph[nt >> 1][(nt & 1) * 2 + 1] = pack_h2(p10, p11);
        }

        // ---- O += P V (V^T frags via ldmatrix.trans, split V) ----
        const uint32_t aVh = kvb + 2 * KV_MAT + vrow * AROWB + vcol;
#pragma unroll
        for (int ks = 0; ks < 4; ks++)
#pragma unroll
            for (int dt2 = 0; dt2 < 4; dt2++) {
                uint32_t vh_[4], vl_[4];
                ldsm_x4_t(vh_, aVh + ks * (16 * AROWB) + dt2 * 32);
                ldsm_x4_t(vl_, aVh + KV_MAT + ks * (16 * AROWB) + dt2 * 32);
                uint32_t f0[2] = { vh_[0], vh_[2] }, f1[2] = { vh_[1], vh_[3] };
                uint32_t e0[2] = { vl_[0], vl_[2] }, e1[2] = { vl_[1], vl_[3] };
                mma_f16(oacc[dt2 * 2 + 0], ph[ks], f0);
                mma_f16(oacc[dt2 * 2 + 0], ph[ks], e0);
                mma_f16(oacc[dt2 * 2 + 1], ph[ks], f1);
                mma_f16(oacc[dt2 * 2 + 1], ph[ks], e1);
            }
        __syncthreads();
    }

    // ---- normalize + store ----
    lsum0 += __shfl_xor_sync(0xffffffffu, lsum0, 1);
    lsum0 += __shfl_xor_sync(0xffffffffu, lsum0, 2);
    lsum1 += __shfl_xor_sync(0xffffffffu, lsum1, 1);
    lsum1 += __shfl_xor_sync(0xffffffffu, lsum1, 2);
    float inv0 = 1.f / lsum0, inv1 = 1.f / lsum1;

    float* o0 = &g_O[((size_t)b * SEQ + qr0) * EMBED + h * 64 + (lane & 3) * 2];
    float* o1 = o0 + (size_t)8 * EMBED;
#pragma unroll
    for (int dt = 0; dt < 8; dt++) {
        *(float2*)(o0 + dt * 8) = make_float2(oacc[dt][0] * inv0, oacc[dt][1] * inv0);
        *(float2*)(o1 + dt * 8) = make_float2(oacc[dt][2] * inv1, oacc[dt][3] * inv1);
    }
}

// ---------------------------------------------------------------------------
extern "C" void kernel_launch(void* const* d_in, const int* in_sizes, int n_in,
                              void* d_out, int out_size)
{
    const float* x    = (const float*)d_in[0];
    const int*   mask = (const int*)  d_in[1];
    const float* Wq   = (const float*)d_in[2];
    const float* bq   = (const float*)d_in[3];
    const float* Wk   = (const float*)d_in[4];
    const float* bk   = (const float*)d_in[5];
    const float* Wv   = (const float*)d_in[6];
    const float* bv   = (const float*)d_in[7];
    const float* Wo   = (const float*)d_in[8];
    const float* bo   = (const float*)d_in[9];

    __nv_bfloat16 *xhi, *xlo, *ohi, *olo, *wthi, *wtlo;
    float* oO;
    cudaGetSymbolAddress((void**)&xhi,  g_xhi);
    cudaGetSymbolAddress((void**)&xlo,  g_xlo);
    cudaGetSymbolAddress((void**)&ohi,  g_ohi);
    cudaGetSymbolAddress((void**)&olo,  g_olo);
    cudaGetSymbolAddress((void**)&wthi, g_wthi);
    cudaGetSymbolAddress((void**)&wtlo, g_wtlo);
    cudaGetSymbolAddress((void**)&oO,   g_O);

    const size_t WSZ = (size_t)NDIM * KDIM;
    int n4x = MTOT * KDIM / 4;

    split_kernel<<<(n4x + 255) / 256, 256>>>(x, xhi, xlo, n4x);

    dim3 wg(NDIM / 32, KDIM / 32);
    wsplit_kernel<<<wg, 256>>>(Wq, wthi + 0 * WSZ, wtlo + 0 * WSZ);
    wsplit_kernel<<<wg, 256>>>(Wk, wthi + 1 * WSZ, wtlo + 1 * WSZ);
    wsplit_kernel<<<wg, 256>>>(Wv, wthi + 2 * WSZ, wtlo + 2 * WSZ);
    wsplit_kernel<<<wg, 256>>>(Wo, wthi + 3 * WSZ, wtlo + 3 * WSZ);

    pack_mask<<<2048, 256>>>(mask);

    cudaFuncSetAttribute(gemm_mma, cudaFuncAttributeMaxDynamicSharedMemorySize, GEMM_SMEM);
    dim3 gg(NDIM / 128, MTOT / 128);
    gemm_mma<<<gg, 256, GEMM_SMEM>>>(xhi, xlo, wthi + 0 * WSZ, wtlo + 0 * WSZ, bq, nullptr, 0);
    gemm_mma<<<gg, 256, GEMM_SMEM>>>(xhi, xlo, wthi + 1 * WSZ, wtlo + 1 * WSZ, bk, nullptr, 1);
    gemm_mma<<<gg, 256, GEMM_SMEM>>>(xhi, xlo, wthi + 2 * WSZ, wtlo + 2 * WSZ, bv, nullptr, 2);

    cudaFuncSetAttribute(attn_mma, cudaFuncAttributeMaxDynamicSharedMemorySize, ATT_SMEM);
    dim3 ga(SEQ / 128, NB * NHEADS);
    attn_mma<<<ga, 256, ATT_SMEM>>>();

    split_kernel<<<(n4x + 255) / 256, 256>>>(oO, ohi, olo, n4x);
    gemm_mma<<<gg, 256, GEMM_SMEM>>>(ohi, olo, wthi + 3 * WSZ, wtlo + 3 * WSZ, bo, (float*)d_out, 3);
}

// round 7
// speedup vs baseline: 2.9209x; 1.2185x over previous
#include <cuda_runtime.h>
#include <cuda_bf16.h>
#include <cuda_fp16.h>
#include <cstdint>

#define EMBED   1024
#define NHEADS  16
#define HDIM    64
#define NB      4
#define SEQ     2048
#define MTOT    (NB*SEQ)
#define KDIM    1024
#define NDIM    1024
#define QSCALE  0.18033688011112042f  /* 0.125 * log2(e) */

// ---- device-global scratch ----
__device__ __half g_q[(size_t)NB*NHEADS*SEQ*HDIM];
__device__ __half g_k[(size_t)NB*NHEADS*SEQ*HDIM];
__device__ __half g_v[(size_t)NB*NHEADS*SEQ*HDIM];
__device__ __nv_bfloat16 g_xhi[(size_t)MTOT*KDIM];
__device__ __nv_bfloat16 g_xlo[(size_t)MTOT*KDIM];
__device__ __nv_bfloat16 g_ohi[(size_t)MTOT*EMBED];
__device__ __nv_bfloat16 g_olo[(size_t)MTOT*EMBED];
__device__ __nv_bfloat16 g_wthi[(size_t)4*NDIM*KDIM];
__device__ __nv_bfloat16 g_wtlo[(size_t)4*NDIM*KDIM];
__device__ uint32_t g_mpack[(size_t)NB*SEQ*(SEQ/32)];

// ---- PTX helpers ----
__device__ __forceinline__ uint32_t smem_u32(const void* p) {
    uint32_t a;
    asm("{ .reg .u64 t; cvta.to.shared.u64 t, %1; cvt.u32.u64 %0, t; }" : "=r"(a) : "l"(p));
    return a;
}
__device__ __forceinline__ void ldsm_x4(uint32_t* r, uint32_t addr) {
    asm volatile("ldmatrix.sync.aligned.m8n8.x4.shared.b16 {%0,%1,%2,%3}, [%4];"
        : "=r"(r[0]), "=r"(r[1]), "=r"(r[2]), "=r"(r[3]) : "r"(addr));
}
__device__ __forceinline__ void ldsm_x4_t(uint32_t* r, uint32_t addr) {
    asm volatile("ldmatrix.sync.aligned.m8n8.x4.trans.shared.b16 {%0,%1,%2,%3}, [%4];"
        : "=r"(r[0]), "=r"(r[1]), "=r"(r[2]), "=r"(r[3]) : "r"(addr));
}
__device__ __forceinline__ void mma_bf16(float* c, const uint32_t* a, const uint32_t* b) {
    asm volatile("mma.sync.aligned.m16n8k16.row.col.f32.bf16.bf16.f32 "
        "{%0,%1,%2,%3}, {%4,%5,%6,%7}, {%8,%9}, {%0,%1,%2,%3};"
        : "+f"(c[0]), "+f"(c[1]), "+f"(c[2]), "+f"(c[3])
        : "r"(a[0]), "r"(a[1]), "r"(a[2]), "r"(a[3]), "r"(b[0]), "r"(b[1]));
}
__device__ __forceinline__ void mma_f16(float* c, const uint32_t* a, const uint32_t* b) {
    asm volatile("mma.sync.aligned.m16n8k16.row.col.f32.f16.f16.f32 "
        "{%0,%1,%2,%3}, {%4,%5,%6,%7}, {%8,%9}, {%0,%1,%2,%3};"
        : "+f"(c[0]), "+f"(c[1]), "+f"(c[2]), "+f"(c[3])
        : "r"(a[0]), "r"(a[1]), "r"(a[2]), "r"(a[3]), "r"(b[0]), "r"(b[1]));
}
__device__ __forceinline__ void cp16(uint32_t dst, const void* src) {
    asm volatile("cp.async.cg.shared.global [%0], [%1], 16;"
        :: "r"(dst), "l"(__cvta_generic_to_global(src)));
}
__device__ __forceinline__ float ex2f(float y) {
    float r; asm("ex2.approx.f32 %0, %1;" : "=f"(r) : "f"(y)); return r;
}
__device__ __forceinline__ uint32_t pack_h2(float a, float b) {
    __half2 h = __halves2half2(__float2half_rn(a), __float2half_rn(b));
    return *(uint32_t*)&h;
}

// ---- split fp32 -> bf16 hi/lo ----
__global__ void __launch_bounds__(256) split_kernel(
    const float* __restrict__ in, __nv_bfloat16* __restrict__ hi,
    __nv_bfloat16* __restrict__ lo, int n4)
{
    int i = blockIdx.x * 256 + threadIdx.x;
    if (i >= n4) return;
    float4 v = ((const float4*)in)[i];
    __nv_bfloat16 h0 = __float2bfloat16(v.x), h1 = __float2bfloat16(v.y);
    __nv_bfloat16 h2 = __float2bfloat16(v.z), h3 = __float2bfloat16(v.w);
    ((__nv_bfloat162*)hi)[2*i]   = __nv_bfloat162(h0, h1);
    ((__nv_bfloat162*)hi)[2*i+1] = __nv_bfloat162(h2, h3);
    ((__nv_bfloat162*)lo)[2*i]   = __nv_bfloat162(
        __float2bfloat16(v.x - __bfloat162float(h0)), __float2bfloat16(v.y - __bfloat162float(h1)));
    ((__nv_bfloat162*)lo)[2*i+1] = __nv_bfloat162(
        __float2bfloat16(v.z - __bfloat162float(h2)), __float2bfloat16(v.w - __bfloat162float(h3)));
}

// ---- transpose+split W ----
__global__ void __launch_bounds__(256) wsplit_kernel(
    const float* __restrict__ W, __nv_bfloat16* __restrict__ hi, __nv_bfloat16* __restrict__ lo)
{
    __shared__ float tile[32][33];
    int tx = threadIdx.x & 31, ty0 = threadIdx.x >> 5;
    int bn = blockIdx.x * 32, bk = blockIdx.y * 32;
#pragma unroll
    for (int i = 0; i < 4; i++)
        tile[ty0 + i*8][tx] = W[(size_t)(bk + ty0 + i*8) * NDIM + bn + tx];
    __syncthreads();
#pragma unroll
    for (int i = 0; i < 4; i++) {
        int ty = ty0 + i * 8;
        float v = tile[tx][ty];
        __nv_bfloat16 h = __float2bfloat16(v);
        size_t o = (size_t)(bn + ty) * KDIM + bk + tx;
        hi[o] = h;
        lo[o] = __float2bfloat16(v - __bfloat162float(h));
    }
}

// ---- pack mask to bits ----
__global__ void __launch_bounds__(256) pack_mask(const int* __restrict__ m)
{
    int gw = (blockIdx.x * 256 + threadIdx.x) >> 5;
    int lane = threadIdx.x & 31;
    size_t base = (size_t)gw * 1024;
#pragma unroll 4
    for (int i = 0; i < 32; i++) {
        uint32_t bal = __ballot_sync(0xffffffffu, m[base + i*32 + lane] != 0);
        if (lane == 0) g_mpack[(size_t)gw * 32 + i] = bal;
    }
}

// ---- split-bf16 tensor GEMM (fp16 epilogue for QKV, fp32 for output) ----
#define ROWB      80
#define MAT_BYTES (128*ROWB)
#define STG_BYTES (4*MAT_BYTES)
#define GEMM_SMEM (2*STG_BYTES)
#define OFF_ALO   MAT_BYTES
#define OFF_BHI   (2*MAT_BYTES)
#define OFF_BLO   (3*MAT_BYTES)

__global__ void __launch_bounds__(256, 1) gemm_mma(
    const __nv_bfloat16* __restrict__ Ahi, const __nv_bfloat16* __restrict__ Alo,
    const __nv_bfloat16* __restrict__ Bhi, const __nv_bfloat16* __restrict__ Blo,
    const float* __restrict__ bias, float* __restrict__ Cout, int mode)
{
    extern __shared__ char sm[];
    const uint32_t sb = smem_u32(sm);
    const int t = threadIdx.x, lane = t & 31, wid = t >> 5;
    const int wm = wid >> 2, wn = wid & 3;
    const int bm = blockIdx.y * 128, bn = blockIdx.x * 128;
    const int r0s = t >> 2, seg0 = t & 3;
    const int r1s = (t + 256) >> 2, seg1 = (t + 256) & 3;
    const int a_row = lane & 15, a_half = lane >> 4;
    const int b_row = ((lane >> 4) << 3) + (lane & 7), b_half = (lane >> 3) & 1;

    float acc[16][4];
#pragma unroll
    for (int i = 0; i < 16; i++)
#pragma unroll
        for (int j = 0; j < 4; j++) acc[i][j] = 0.f;

    const size_t a0g = (size_t)(bm + r0s) * KDIM + seg0 * 8;
    const size_t a1g = (size_t)(bm + r1s) * KDIM + seg1 * 8;
    const size_t b0g = (size_t)(bn + r0s) * KDIM + seg0 * 8;
    const size_t b1g = (size_t)(bn + r1s) * KDIM + seg1 * 8;
    const uint32_t s0 = (uint32_t)(r0s * ROWB + seg0 * 16);
    const uint32_t s1 = (uint32_t)(r1s * ROWB + seg1 * 16);

    {
        *(uint4*)(sm + s0) = *(const uint4*)(Ahi + a0g);
        *(uint4*)(sm + s1) = *(const uint4*)(Ahi + a1g);
        *(uint4*)(sm + OFF_ALO + s0) = *(const uint4*)(Alo + a0g);
        *(uint4*)(sm + OFF_ALO + s1) = *(const uint4*)(Alo + a1g);
        *(uint4*)(sm + OFF_BHI + s0) = *(const uint4*)(Bhi + b0g);
        *(uint4*)(sm + OFF_BHI + s1) = *(const uint4*)(Bhi + b1g);
        *(uint4*)(sm + OFF_BLO + s0) = *(const uint4*)(Blo + b0g);
        *(uint4*)(sm + OFF_BLO + s1) = *(const uint4*)(Blo + b1g);
    }
    __syncthreads();

    const int NSTG = KDIM / 32;
    for (int s = 0; s < NSTG; s++) {
        uint4 vah0, vah1, val0, val1, vbh0, vbh1, vbl0, vbl1;
        if (s + 1 < NSTG) {
            int k0 = (s + 1) * 32;
            vah0 = *(const uint4*)(Ahi + a0g + k0); vah1 = *(const uint4*)(Ahi + a1g + k0);
            val0 = *(const uint4*)(Alo + a0g + k0); val1 = *(const uint4*)(Alo + a1g + k0);
            vbh0 = *(const uint4*)(Bhi + b0g + k0); vbh1 = *(const uint4*)(Bhi + b1g + k0);
            vbl0 = *(const uint4*)(Blo + b0g + k0); vbl1 = *(const uint4*)(Blo + b1g + k0);
        }
        const uint32_t stg = sb + (uint32_t)((s & 1) * STG_BYTES);
        const uint32_t aAhi = stg + (uint32_t)((wm * 64 + a_row) * ROWB + a_half * 16);
        const uint32_t aAlo = aAhi + MAT_BYTES;
        const uint32_t aBhi = stg + OFF_BHI + (uint32_t)((wn * 32 + b_row) * ROWB + b_half * 16);
        const uint32_t aBlo = aBhi + MAT_BYTES;
#pragma unroll
        for (int kk = 0; kk < 2; kk++) {
            uint32_t ah[4][4], al[4][4], bh[2][4], bl[2][4];
            const uint32_t koff = (uint32_t)(kk * 32);
#pragma unroll
            for (int mt = 0; mt < 4; mt++) {
                ldsm_x4(ah[mt], aAhi + mt * (16 * ROWB) + koff);
                ldsm_x4(al[mt], aAlo + mt * (16 * ROWB) + koff);
            }
#pragma unroll
            for (int nt = 0; nt < 2; nt++) {
                ldsm_x4(bh[nt], aBhi + nt * (16 * ROWB) + koff);
                ldsm_x4(bl[nt], aBlo + nt * (16 * ROWB) + koff);
            }
#pragma unroll
            for (int mt = 0; mt < 4; mt++)
#pragma unroll
                for (int j = 0; j < 4; j++) {
                    const uint32_t* bhf = &bh[j >> 1][(j & 1) * 2];
                    const uint32_t* blf = &bl[j >> 1][(j & 1) * 2];
                    float* c = acc[mt * 4 + j];
                    mma_bf16(c, ah[mt], bhf);
                    mma_bf16(c, ah[mt], blf);
                    mma_bf16(c, al[mt], bhf);
                }
        }
        if (s + 1 < NSTG) {
            char* dst = sm + ((s + 1) & 1) * STG_BYTES;
            *(uint4*)(dst + s0) = vah0;           *(uint4*)(dst + s1) = vah1;
            *(uint4*)(dst + OFF_ALO + s0) = val0; *(uint4*)(dst + OFF_ALO + s1) = val1;
            *(uint4*)(dst + OFF_BHI + s0) = vbh0; *(uint4*)(dst + OFF_BHI + s1) = vbh1;
            *(uint4*)(dst + OFF_BLO + s0) = vbl0; *(uint4*)(dst + OFF_BLO + s1) = vbl1;
            __syncthreads();
        }
    }

    __half* dsth = (mode == 0) ? g_q : (mode == 1) ? g_k : g_v;
    const float qs = (mode == 0) ? QSCALE : 1.f;
    const int g = lane >> 2, cq = (lane & 3) * 2;
#pragma unroll
    for (int mt = 0; mt < 4; mt++)
#pragma unroll
        for (int j = 0; j < 4; j++) {
            const float* c = acc[mt * 4 + j];
            int row = bm + wm * 64 + mt * 16 + g;
            int col = bn + wn * 32 + j * 8 + cq;
            float b0 = bias[col], b1 = bias[col + 1];
#pragma unroll
            for (int hf = 0; hf < 2; hf++) {
                int r = row + hf * 8;
                float v0 = c[hf * 2] + b0, v1 = c[hf * 2 + 1] + b1;
                if (mode <= 2) {
                    int b_ = r >> 11, l = r & (SEQ - 1), hh = col >> 6, d = col & 63;
                    size_t idx = ((((size_t)b_ * NHEADS + hh) * SEQ) + l) * HDIM + d;
                    *(__half2*)&dsth[idx] =
                        __halves2half2(__float2half_rn(v0 * qs), __float2half_rn(v1 * qs));
                } else {
                    *(float2*)&Cout[(size_t)r * NDIM + col] = make_float2(v0, v1);
                }
            }
        }
}

// ---- fp16 tensor-core flash attention (writes bf16 hi/lo output) ----
#define AROWB    144
#define KV_MAT   (64*AROWB)         /* 9216 */
#define KV_STG   (2*KV_MAT)         /* K + V */
#define AQ_OFF   (2*KV_STG)         /* 36864 */
#define AQ_MAT   (128*AROWB)        /* 18432 */
#define ATT_SMEM (AQ_OFF + AQ_MAT)  /* 55296 */

__global__ void __launch_bounds__(256, 1) attn_mma()
{
    extern __shared__ char sm[];
    const uint32_t sb = smem_u32(sm);
    const int t = threadIdx.x, lane = t & 31, wid = t >> 5;
    const int bh = blockIdx.y, b = bh >> 4, h = bh & 15;
    const int qbase = blockIdx.x * 128;

    const __half* Qp = g_q + (size_t)bh * SEQ * HDIM + (size_t)qbase * HDIM;
    const __half* Kp = g_k + (size_t)bh * SEQ * HDIM;
    const __half* Vp = g_v + (size_t)bh * SEQ * HDIM;

    // stage Q into padded smem
#pragma unroll
    for (int j = 0; j < 4; j++) {
        int r = (t >> 3) + j * 32;
        int ch = t & 7;
        *(uint4*)(sm + AQ_OFF + r * AROWB + ch * 16) = *(const uint4*)(Qp + (size_t)r * 64 + ch * 8);
    }
    __syncthreads();

    // Q fragments (16 rows per warp)
    uint32_t qh[4][4];
    {
        uint32_t aq = sb + AQ_OFF + (uint32_t)((wid * 16 + (lane & 15)) * AROWB + (lane >> 4) * 16);
#pragma unroll
        for (int ks = 0; ks < 4; ks++) ldsm_x4(qh[ks], aq + ks * 32);
    }

    const int b_row = ((lane >> 4) << 3) + (lane & 7), b_half = (lane >> 3) & 1;
    const uint32_t vrow = (uint32_t)((lane & 7) + ((lane >> 4) << 3));
    const uint32_t vcol = (uint32_t)(((lane >> 3) & 1) << 4);

    float oacc[8][4];
#pragma unroll
    for (int i = 0; i < 8; i++)
#pragma unroll
        for (int j = 0; j < 4; j++) oacc[i][j] = 0.f;
    float lsum0 = 0.f, lsum1 = 0.f;

    const int qr0 = qbase + wid * 16 + (lane >> 2);
    const uint32_t* mrow = g_mpack + ((size_t)b * SEQ + qr0) * 64;

    // prologue stage kt=0
#pragma unroll
    for (int j = 0; j < 4; j++) {
        int mat = j >> 1;
        int r = (t >> 3) + (j & 1) * 32;
        int ch = t & 7;
        const __half* src = (mat == 0 ? Kp : Vp) + (size_t)r * 64 + ch * 8;
        cp16(sb + mat * KV_MAT + r * AROWB + ch * 16, src);
    }
    asm volatile("cp.async.commit_group;");

    for (int kt = 0; kt < SEQ / 64; kt++) {
        if (kt + 1 < SEQ / 64) {
            int kb = (kt + 1) * 64;
            uint32_t dstb = sb + ((kt + 1) & 1) * KV_STG;
#pragma unroll
            for (int j = 0; j < 4; j++) {
                int mat = j >> 1;
                int r = (t >> 3) + (j & 1) * 32;
                int ch = t & 7;
                const __half* src = (mat == 0 ? Kp : Vp) + (size_t)(kb + r) * 64 + ch * 8;
                cp16(dstb + mat * KV_MAT + r * AROWB + ch * 16, src);
            }
            asm volatile("cp.async.commit_group;");
            asm volatile("cp.async.wait_group 1;");
        } else {
            asm volatile("cp.async.wait_group 0;");
        }
        __syncthreads();

        const uint32_t kvb = sb + (kt & 1) * KV_STG;

        // ---- S = Q K^T (fp16), fp32 accum ----
        float sacc[8][4];
#pragma unroll
        for (int i = 0; i < 8; i++)
#pragma unroll
            for (int j = 0; j < 4; j++) sacc[i][j] = 0.f;

        const uint32_t aK = kvb + (uint32_t)(b_row * AROWB + b_half * 16);
#pragma unroll
        for (int ks = 0; ks < 4; ks++)
#pragma unroll
            for (int nt2 = 0; nt2 < 4; nt2++) {
                uint32_t bh_[4];
                ldsm_x4(bh_, aK + nt2 * (16 * AROWB) + ks * 32);
                mma_f16(sacc[nt2 * 2 + 0], qh[ks], &bh_[0]);
                mma_f16(sacc[nt2 * 2 + 1], qh[ks], &bh_[2]);
            }

        // ---- mask + 2^y + repack P into A-fragments ----
        uint32_t m0a = mrow[kt * 2], m0b = mrow[kt * 2 + 1];
        uint32_t m1a = mrow[512 + kt * 2], m1b = mrow[512 + kt * 2 + 1];
        uint32_t ph[4][4];
#pragma unroll
        for (int nt = 0; nt < 8; nt++) {
            int cb = nt * 8 + (lane & 3) * 2;
            uint32_t w0 = (nt < 4) ? m0a : m0b;
            uint32_t w1 = (nt < 4) ? m1a : m1b;
            int sh = cb & 31;
            float y00 = ((w0 >> sh) & 1) ? sacc[nt][0] : -24.f;
            float y01 = ((w0 >> (sh + 1)) & 1) ? sacc[nt][1] : -24.f;
            float y10 = ((w1 >> sh) & 1) ? sacc[nt][2] : -24.f;
            float y11 = ((w1 >> (sh + 1)) & 1) ? sacc[nt][3] : -24.f;
            float p00 = ex2f(y00), p01 = ex2f(y01), p10 = ex2f(y10), p11 = ex2f(y11);
            lsum0 += p00 + p01;
            lsum1 += p10 + p11;
            ph[nt >> 1][(nt & 1) * 2 + 0] = pack_h2(p00, p01);
            ph[nt >> 1][(nt & 1) * 2 + 1] = pack_h2(p10, p11);
        }

        // ---- O += P V ----
        const uint32_t aV = kvb + KV_MAT + vrow * AROWB + vcol;
#pragma unroll
        for (int ks = 0; ks < 4; ks++)
#pragma unroll
            for (int dt2 = 0; dt2 < 4; dt2++) {
                uint32_t vh_[4];
                ldsm_x4_t(vh_, aV + ks * (16 * AROWB) + dt2 * 32);
                uint32_t f0[2] = { vh_[0], vh_[2] }, f1[2] = { vh_[1], vh_[3] };
                mma_f16(oacc[dt2 * 2 + 0], ph[ks], f0);
                mma_f16(oacc[dt2 * 2 + 1], ph[ks], f1);
            }
        __syncthreads();
    }

    // ---- normalize + split-store bf16 hi/lo ----
    lsum0 += __shfl_xor_sync(0xffffffffu, lsum0, 1);
    lsum0 += __shfl_xor_sync(0xffffffffu, lsum0, 2);
    lsum1 += __shfl_xor_sync(0xffffffffu, lsum1, 1);
    lsum1 += __shfl_xor_sync(0xffffffffu, lsum1, 2);
    float inv0 = 1.f / lsum0, inv1 = 1.f / lsum1;

    const int col0 = h * 64 + (lane & 3) * 2;
    size_t row0 = (size_t)b * SEQ + qr0;
#pragma unroll
    for (int dt = 0; dt < 8; dt++) {
#pragma unroll
        for (int hf = 0; hf < 2; hf++) {
            float v0 = oacc[dt][hf * 2 + 0] * (hf ? inv1 : inv0);
            float v1 = oacc[dt][hf * 2 + 1] * (hf ? inv1 : inv0);
            size_t idx = (row0 + hf * 8) * EMBED + col0 + dt * 8;
            __nv_bfloat16 h0 = __float2bfloat16(v0), h1 = __float2bfloat16(v1);
            *(__nv_bfloat162*)&g_ohi[idx] = __nv_bfloat162(h0, h1);
            *(__nv_bfloat162*)&g_olo[idx] = __nv_bfloat162(
                __float2bfloat16(v0 - __bfloat162float(h0)),
                __float2bfloat16(v1 - __bfloat162float(h1)));
        }
    }
}

// ---------------------------------------------------------------------------
extern "C" void kernel_launch(void* const* d_in, const int* in_sizes, int n_in,
                              void* d_out, int out_size)
{
    const float* x    = (const float*)d_in[0];
    const int*   mask = (const int*)  d_in[1];
    const float* Wq   = (const float*)d_in[2];
    const float* bq   = (const float*)d_in[3];
    const float* Wk   = (const float*)d_in[4];
    const float* bk   = (const float*)d_in[5];
    const float* Wv   = (const float*)d_in[6];
    const float* bv   = (const float*)d_in[7];
    const float* Wo   = (const float*)d_in[8];
    const float* bo   = (const float*)d_in[9];

    __nv_bfloat16 *xhi, *xlo, *ohi, *olo, *wthi, *wtlo;
    cudaGetSymbolAddress((void**)&xhi,  g_xhi);
    cudaGetSymbolAddress((void**)&xlo,  g_xlo);
    cudaGetSymbolAddress((void**)&ohi,  g_ohi);
    cudaGetSymbolAddress((void**)&olo,  g_olo);
    cudaGetSymbolAddress((void**)&wthi, g_wthi);
    cudaGetSymbolAddress((void**)&wtlo, g_wtlo);

    const size_t WSZ = (size_t)NDIM * KDIM;
    int n4x = MTOT * KDIM / 4;

    split_kernel<<<(n4x + 255) / 256, 256>>>(x, xhi, xlo, n4x);

    dim3 wg(NDIM / 32, KDIM / 32);
    wsplit_kernel<<<wg, 256>>>(Wq, wthi + 0 * WSZ, wtlo + 0 * WSZ);
    wsplit_kernel<<<wg, 256>>>(Wk, wthi + 1 * WSZ, wtlo + 1 * WSZ);
    wsplit_kernel<<<wg, 256>>>(Wv, wthi + 2 * WSZ, wtlo + 2 * WSZ);
    wsplit_kernel<<<wg, 256>>>(Wo, wthi + 3 * WSZ, wtlo + 3 * WSZ);

    pack_mask<<<2048, 256>>>(mask);

    cudaFuncSetAttribute(gemm_mma, cudaFuncAttributeMaxDynamicSharedMemorySize, GEMM_SMEM);
    dim3 gg(NDIM / 128, MTOT / 128);
    gemm_mma<<<gg, 256, GEMM_SMEM>>>(xhi, xlo, wthi + 0 * WSZ, wtlo + 0 * WSZ, bq, nullptr, 0);
    gemm_mma<<<gg, 256, GEMM_SMEM>>>(xhi, xlo, wthi + 1 * WSZ, wtlo + 1 * WSZ, bk, nullptr, 1);
    gemm_mma<<<gg, 256, GEMM_SMEM>>>(xhi, xlo, wthi + 2 * WSZ, wtlo + 2 * WSZ, bv, nullptr, 2);

    cudaFuncSetAttribute(attn_mma, cudaFuncAttributeMaxDynamicSharedMemorySize, ATT_SMEM);
    dim3 ga(SEQ / 128, NB * NHEADS);
    attn_mma<<<ga, 256, ATT_SMEM>>>();

    gemm_mma<<<gg, 256, GEMM_SMEM>>>(ohi, olo, wthi + 3 * WSZ, wtlo + 3 * WSZ, bo, (float*)d_out, 3);
}

// round 8
// speedup vs baseline: 3.0266x; 1.0362x over previous
#include <cuda_runtime.h>
#include <cuda_bf16.h>
#include <cuda_fp16.h>
#include <cstdint>

#define EMBED   1024
#define NHEADS  16
#define HDIM    64
#define NB      4
#define SEQ     2048
#define MTOT    (NB*SEQ)
#define KDIM    1024
#define NDIM    1024
#define QSCALE  0.18033688011112042f  /* 0.125 * log2(e) */

// ---- device-global scratch ----
__device__ __half g_q[(size_t)NB*NHEADS*SEQ*HDIM];
__device__ __half g_k[(size_t)NB*NHEADS*SEQ*HDIM];
__device__ __half g_v[(size_t)NB*NHEADS*SEQ*HDIM];
__device__ __nv_bfloat16 g_xhi[(size_t)MTOT*KDIM];
__device__ __nv_bfloat16 g_xlo[(size_t)MTOT*KDIM];
__device__ __nv_bfloat16 g_ohi[(size_t)MTOT*EMBED];
__device__ __nv_bfloat16 g_olo[(size_t)MTOT*EMBED];
__device__ __nv_bfloat16 g_wthi[(size_t)4*NDIM*KDIM];
__device__ __nv_bfloat16 g_wtlo[(size_t)4*NDIM*KDIM];
__device__ uint32_t g_mpack[(size_t)NB*SEQ*(SEQ/32)];

// ---- PTX helpers ----
__device__ __forceinline__ uint32_t smem_u32(const void* p) {
    uint32_t a;
    asm("{ .reg .u64 t; cvta.to.shared.u64 t, %1; cvt.u32.u64 %0, t; }" : "=r"(a) : "l"(p));
    return a;
}
__device__ __forceinline__ void ldsm_x4(uint32_t* r, uint32_t addr) {
    asm volatile("ldmatrix.sync.aligned.m8n8.x4.shared.b16 {%0,%1,%2,%3}, [%4];"
        : "=r"(r[0]), "=r"(r[1]), "=r"(r[2]), "=r"(r[3]) : "r"(addr));
}
__device__ __forceinline__ void ldsm_x4_t(uint32_t* r, uint32_t addr) {
    asm volatile("ldmatrix.sync.aligned.m8n8.x4.trans.shared.b16 {%0,%1,%2,%3}, [%4];"
        : "=r"(r[0]), "=r"(r[1]), "=r"(r[2]), "=r"(r[3]) : "r"(addr));
}
__device__ __forceinline__ void mma_bf16(float* c, const uint32_t* a, const uint32_t* b) {
    asm volatile("mma.sync.aligned.m16n8k16.row.col.f32.bf16.bf16.f32 "
        "{%0,%1,%2,%3}, {%4,%5,%6,%7}, {%8,%9}, {%0,%1,%2,%3};"
        : "+f"(c[0]), "+f"(c[1]), "+f"(c[2]), "+f"(c[3])
        : "r"(a[0]), "r"(a[1]), "r"(a[2]), "r"(a[3]), "r"(b[0]), "r"(b[1]));
}
__device__ __forceinline__ void mma_f16(float* c, const uint32_t* a, const uint32_t* b) {
    asm volatile("mma.sync.aligned.m16n8k16.row.col.f32.f16.f16.f32 "
        "{%0,%1,%2,%3}, {%4,%5,%6,%7}, {%8,%9}, {%0,%1,%2,%3};"
        : "+f"(c[0]), "+f"(c[1]), "+f"(c[2]), "+f"(c[3])
        : "r"(a[0]), "r"(a[1]), "r"(a[2]), "r"(a[3]), "r"(b[0]), "r"(b[1]));
}
__device__ __forceinline__ void cp16(uint32_t dst, const void* src) {
    asm volatile("cp.async.cg.shared.global [%0], [%1], 16;"
        :: "r"(dst), "l"(__cvta_generic_to_global(src)));
}
__device__ __forceinline__ float ex2f(float y) {
    float r; asm("ex2.approx.f32 %0, %1;" : "=f"(r) : "f"(y)); return r;
}
__device__ __forceinline__ uint32_t pack_h2(float a, float b) {
    __half2 h = __halves2half2(__float2half_rn(a), __float2half_rn(b));
    return *(uint32_t*)&h;
}

// ---- split fp32 -> bf16 hi/lo (x only) ----
__global__ void __launch_bounds__(256) split_kernel(
    const float* __restrict__ in, __nv_bfloat16* __restrict__ hi,
    __nv_bfloat16* __restrict__ lo, int n4)
{
    int i = blockIdx.x * 256 + threadIdx.x;
    if (i >= n4) return;
    float4 v = ((const float4*)in)[i];
    __nv_bfloat16 h0 = __float2bfloat16(v.x), h1 = __float2bfloat16(v.y);
    __nv_bfloat16 h2 = __float2bfloat16(v.z), h3 = __float2bfloat16(v.w);
    ((__nv_bfloat162*)hi)[2*i]   = __nv_bfloat162(h0, h1);
    ((__nv_bfloat162*)hi)[2*i+1] = __nv_bfloat162(h2, h3);
    ((__nv_bfloat162*)lo)[2*i]   = __nv_bfloat162(
        __float2bfloat16(v.x - __bfloat162float(h0)), __float2bfloat16(v.y - __bfloat162float(h1)));
    ((__nv_bfloat162*)lo)[2*i+1] = __nv_bfloat162(
        __float2bfloat16(v.z - __bfloat162float(h2)), __float2bfloat16(v.w - __bfloat162float(h3)));
}

// ---- transpose+split all 4 W in one launch (blockIdx.z selects matrix) ----
__global__ void __launch_bounds__(256) wsplit_kernel(
    const float* __restrict__ W0, const float* __restrict__ W1,
    const float* __restrict__ W2, const float* __restrict__ W3,
    __nv_bfloat16* __restrict__ hi_base, __nv_bfloat16* __restrict__ lo_base)
{
    __shared__ float tile[32][33];
    const float* W = (blockIdx.z == 0) ? W0 : (blockIdx.z == 1) ? W1 :
                     (blockIdx.z == 2) ? W2 : W3;
    __nv_bfloat16* hi = hi_base + (size_t)blockIdx.z * NDIM * KDIM;
    __nv_bfloat16* lo = lo_base + (size_t)blockIdx.z * NDIM * KDIM;
    int tx = threadIdx.x & 31, ty0 = threadIdx.x >> 5;
    int bn = blockIdx.x * 32, bk = blockIdx.y * 32;
#pragma unroll
    for (int i = 0; i < 4; i++)
        tile[ty0 + i*8][tx] = W[(size_t)(bk + ty0 + i*8) * NDIM + bn + tx];
    __syncthreads();
#pragma unroll
    for (int i = 0; i < 4; i++) {
        int ty = ty0 + i * 8;
        float v = tile[tx][ty];
        __nv_bfloat16 h = __float2bfloat16(v);
        size_t o = (size_t)(bn + ty) * KDIM + bk + tx;
        hi[o] = h;
        lo[o] = __float2bfloat16(v - __bfloat162float(h));
    }
}

// ---- pack mask to bits ----
__global__ void __launch_bounds__(256) pack_mask(const int* __restrict__ m)
{
    int gw = (blockIdx.x * 256 + threadIdx.x) >> 5;
    int lane = threadIdx.x & 31;
    size_t base = (size_t)gw * 1024;
#pragma unroll 4
    for (int i = 0; i < 32; i++) {
        uint32_t bal = __ballot_sync(0xffffffffu, m[base + i*32 + lane] != 0);
        if (lane == 0) g_mpack[(size_t)gw * 32 + i] = bal;
    }
}

// ---- split-bf16 tensor GEMM v2: 128 thr, 4 warps @ 64x64, all-cp.async ----
#define ROWB      80
#define MAT_BYTES (128*ROWB)          /* 10240 */
#define STG_BYTES (4*MAT_BYTES)       /* 40960 */
#define GEMM_SMEM (2*STG_BYTES)       /* 81920 */
#define OFF_ALO   MAT_BYTES
#define OFF_BHI   (2*MAT_BYTES)
#define OFF_BLO   (3*MAT_BYTES)

__global__ void __launch_bounds__(128) gemm_mma(
    const __nv_bfloat16* __restrict__ Ahi, const __nv_bfloat16* __restrict__ Alo,
    const __nv_bfloat16* __restrict__ Bhi, const __nv_bfloat16* __restrict__ Blo,
    const float* __restrict__ bias, float* __restrict__ Cout, int mode)
{
    extern __shared__ char sm[];
    const uint32_t sb = smem_u32(sm);
    const int t = threadIdx.x, lane = t & 31, wid = t >> 5;
    const int wm = wid >> 1, wn = wid & 1;           // 2x2 warp grid, 64x64 tiles
    const int bm = blockIdx.y * 128, bn = blockIdx.x * 128;

    const int a_row = lane & 15, a_half = lane >> 4;
    const int b_row = ((lane >> 4) << 3) + (lane & 7), b_half = (lane >> 3) & 1;

    float acc[32][4];
#pragma unroll
    for (int i = 0; i < 32; i++)
#pragma unroll
        for (int j = 0; j < 4; j++) acc[i][j] = 0.f;

    // cp.async staging indices: thread covers 4 rows per matrix (16B segs)
    const int cr = t >> 2, cseg = t & 3;

    // prologue: stage 0
    {
        const int k0 = 0;
#pragma unroll
        for (int j = 0; j < 4; j++) {
            int r = cr + j * 32;
            uint32_t d = sb + (uint32_t)(r * ROWB + cseg * 16);
            size_t ga = (size_t)(bm + r) * KDIM + k0 + cseg * 8;
            size_t gb = (size_t)(bn + r) * KDIM + k0 + cseg * 8;
            cp16(d,                    Ahi + ga);
            cp16(d + OFF_ALO,          Alo + ga);
            cp16(d + OFF_BHI,          Bhi + gb);
            cp16(d + OFF_BLO,          Blo + gb);
        }
        asm volatile("cp.async.commit_group;");
    }

    const int NSTG = KDIM / 32;
    for (int s = 0; s < NSTG; s++) {
        if (s + 1 < NSTG) {
            const int k0 = (s + 1) * 32;
            const uint32_t stg = sb + (uint32_t)(((s + 1) & 1) * STG_BYTES);
#pragma unroll
            for (int j = 0; j < 4; j++) {
                int r = cr + j * 32;
                uint32_t d = stg + (uint32_t)(r * ROWB + cseg * 16);
                size_t ga = (size_t)(bm + r) * KDIM + k0 + cseg * 8;
                size_t gb = (size_t)(bn + r) * KDIM + k0 + cseg * 8;
                cp16(d,                    Ahi + ga);
                cp16(d + OFF_ALO,          Alo + ga);
                cp16(d + OFF_BHI,          Bhi + gb);
                cp16(d + OFF_BLO,          Blo + gb);
            }
            asm volatile("cp.async.commit_group;");
            asm volatile("cp.async.wait_group 1;");
        } else {
            asm volatile("cp.async.wait_group 0;");
        }
        __syncthreads();

        const uint32_t stg = sb + (uint32_t)((s & 1) * STG_BYTES);
        const uint32_t aAhi = stg + (uint32_t)((wm * 64 + a_row) * ROWB + a_half * 16);
        const uint32_t aAlo = aAhi + MAT_BYTES;
        const uint32_t aBhi = stg + OFF_BHI + (uint32_t)((wn * 64 + b_row) * ROWB + b_half * 16);
        const uint32_t aBlo = aBhi + MAT_BYTES;

#pragma unroll
        for (int kk = 0; kk < 2; kk++) {
            uint32_t ah[4][4], al[4][4], bh[4][4], bl[4][4];
            const uint32_t koff = (uint32_t)(kk * 32);
#pragma unroll
            for (int mt = 0; mt < 4; mt++) {
                ldsm_x4(ah[mt], aAhi + mt * (16 * ROWB) + koff);
                ldsm_x4(al[mt], aAlo + mt * (16 * ROWB) + koff);
            }
#pragma unroll
            for (int nt = 0; nt < 4; nt++) {
                ldsm_x4(bh[nt], aBhi + nt * (16 * ROWB) + koff);
                ldsm_x4(bl[nt], aBlo + nt * (16 * ROWB) + koff);
            }
#pragma unroll
            for (int mt = 0; mt < 4; mt++)
#pragma unroll
                for (int j = 0; j < 8; j++) {
                    const uint32_t* bhf = &bh[j >> 1][(j & 1) * 2];
                    const uint32_t* blf = &bl[j >> 1][(j & 1) * 2];
                    float* c = acc[mt * 8 + j];
                    mma_bf16(c, ah[mt], bhf);
                    mma_bf16(c, ah[mt], blf);
                    mma_bf16(c, al[mt], bhf);
                }
        }
        __syncthreads();
    }

    // epilogue
    __half* dsth = (mode == 0) ? g_q : (mode == 1) ? g_k : g_v;
    const float qs = (mode == 0) ? QSCALE : 1.f;
    const int g = lane >> 2, cq = (lane & 3) * 2;
#pragma unroll
    for (int mt = 0; mt < 4; mt++)
#pragma unroll
        for (int j = 0; j < 8; j++) {
            const float* c = acc[mt * 8 + j];
            int row = bm + wm * 64 + mt * 16 + g;
            int col = bn + wn * 64 + j * 8 + cq;
            float b0 = bias[col], b1 = bias[col + 1];
#pragma unroll
            for (int hf = 0; hf < 2; hf++) {
                int r = row + hf * 8;
                float v0 = c[hf * 2] + b0, v1 = c[hf * 2 + 1] + b1;
                if (mode <= 2) {
                    int b_ = r >> 11, l = r & (SEQ - 1), hh = col >> 6, d = col & 63;
                    size_t idx = ((((size_t)b_ * NHEADS + hh) * SEQ) + l) * HDIM + d;
                    *(__half2*)&dsth[idx] =
                        __halves2half2(__float2half_rn(v0 * qs), __float2half_rn(v1 * qs));
                } else {
                    *(float2*)&Cout[(size_t)r * NDIM + col] = make_float2(v0, v1);
                }
            }
        }
}

// ---- fp16 tensor-core flash attention (unchanged from round 7) ----
#define AROWB    144
#define KV_MAT   (64*AROWB)
#define KV_STG   (2*KV_MAT)
#define AQ_OFF   (2*KV_STG)
#define AQ_MAT   (128*AROWB)
#define ATT_SMEM (AQ_OFF + AQ_MAT)   /* 55296 */

__global__ void __launch_bounds__(256, 1) attn_mma()
{
    extern __shared__ char sm[];
    const uint32_t sb = smem_u32(sm);
    const int t = threadIdx.x, lane = t & 31, wid = t >> 5;
    const int bh = blockIdx.y, b = bh >> 4, h = bh & 15;
    const int qbase = blockIdx.x * 128;

    const __half* Qp = g_q + (size_t)bh * SEQ * HDIM + (size_t)qbase * HDIM;
    const __half* Kp = g_k + (size_t)bh * SEQ * HDIM;
    const __half* Vp = g_v + (size_t)bh * SEQ * HDIM;

#pragma unroll
    for (int j = 0; j < 4; j++) {
        int r = (t >> 3) + j * 32;
        int ch = t & 7;
        *(uint4*)(sm + AQ_OFF + r * AROWB + ch * 16) = *(const uint4*)(Qp + (size_t)r * 64 + ch * 8);
    }
    __syncthreads();

    uint32_t qh[4][4];
    {
        uint32_t aq = sb + AQ_OFF + (uint32_t)((wid * 16 + (lane & 15)) * AROWB + (lane >> 4) * 16);
#pragma unroll
        for (int ks = 0; ks < 4; ks++) ldsm_x4(qh[ks], aq + ks * 32);
    }

    const int b_row = ((lane >> 4) << 3) + (lane & 7), b_half = (lane >> 3) & 1;
    const uint32_t vrow = (uint32_t)((lane & 7) + ((lane >> 4) << 3));
    const uint32_t vcol = (uint32_t)(((lane >> 3) & 1) << 4);

    float oacc[8][4];
#pragma unroll
    for (int i = 0; i < 8; i++)
#pragma unroll
        for (int j = 0; j < 4; j++) oacc[i][j] = 0.f;
    float lsum0 = 0.f, lsum1 = 0.f;

    const int qr0 = qbase + wid * 16 + (lane >> 2);
    const uint32_t* mrow = g_mpack + ((size_t)b * SEQ + qr0) * 64;

#pragma unroll
    for (int j = 0; j < 4; j++) {
        int mat = j >> 1;
        int r = (t >> 3) + (j & 1) * 32;
        int ch = t & 7;
        const __half* src = (mat == 0 ? Kp : Vp) + (size_t)r * 64 + ch * 8;
        cp16(sb + mat * KV_MAT + r * AROWB + ch * 16, src);
    }
    asm volatile("cp.async.commit_group;");

    for (int kt = 0; kt < SEQ / 64; kt++) {
        if (kt + 1 < SEQ / 64) {
            int kb = (kt + 1) * 64;
            uint32_t dstb = sb + ((kt + 1) & 1) * KV_STG;
#pragma unroll
            for (int j = 0; j < 4; j++) {
                int mat = j >> 1;
                int r = (t >> 3) + (j & 1) * 32;
                int ch = t & 7;
                const __half* src = (mat == 0 ? Kp : Vp) + (size_t)(kb + r) * 64 + ch * 8;
                cp16(dstb + mat * KV_MAT + r * AROWB + ch * 16, src);
            }
            asm volatile("cp.async.commit_group;");
            asm volatile("cp.async.wait_group 1;");
        } else {
            asm volatile("cp.async.wait_group 0;");
        }
        __syncthreads();

        const uint32_t kvb = sb + (kt & 1) * KV_STG;

        float sacc[8][4];
#pragma unroll
        for (int i = 0; i < 8; i++)
#pragma unroll
            for (int j = 0; j < 4; j++) sacc[i][j] = 0.f;

        const uint32_t aK = kvb + (uint32_t)(b_row * AROWB + b_half * 16);
#pragma unroll
        for (int ks = 0; ks < 4; ks++)
#pragma unroll
            for (int nt2 = 0; nt2 < 4; nt2++) {
                uint32_t bh_[4];
                ldsm_x4(bh_, aK + nt2 * (16 * AROWB) + ks * 32);
                mma_f16(sacc[nt2 * 2 + 0], qh[ks], &bh_[0]);
                mma_f16(sacc[nt2 * 2 + 1], qh[ks], &bh_[2]);
            }

        uint32_t m0a = mrow[kt * 2], m0b = mrow[kt * 2 + 1];
        uint32_t m1a = mrow[512 + kt * 2], m1b = mrow[512 + kt * 2 + 1];
        uint32_t ph[4][4];
#pragma unroll
        for (int nt = 0; nt < 8; nt++) {
            int cb = nt * 8 + (lane & 3) * 2;
            uint32_t w0 = (nt < 4) ? m0a : m0b;
            uint32_t w1 = (nt < 4) ? m1a : m1b;
            int sh = cb & 31;
            float y00 = ((w0 >> sh) & 1) ? sacc[nt][0] : -24.f;
            float y01 = ((w0 >> (sh + 1)) & 1) ? sacc[nt][1] : -24.f;
            float y10 = ((w1 >> sh) & 1) ? sacc[nt][2] : -24.f;
            float y11 = ((w1 >> (sh + 1)) & 1) ? sacc[nt][3] : -24.f;
            float p00 = ex2f(y00), p01 = ex2f(y01), p10 = ex2f(y10), p11 = ex2f(y11);
            lsum0 += p00 + p01;
            lsum1 += p10 + p11;
            ph[nt >> 1][(nt & 1) * 2 + 0] = pack_h2(p00, p01);
            ph[nt >> 1][(nt & 1) * 2 + 1] = pack_h2(p10, p11);
        }

        const uint32_t aV = kvb + KV_MAT + vrow * AROWB + vcol;
#pragma unroll
        for (int ks = 0; ks < 4; ks++)
#pragma unroll
            for (int dt2 = 0; dt2 < 4; dt2++) {
                uint32_t vh_[4];
                ldsm_x4_t(vh_, aV + ks * (16 * AROWB) + dt2 * 32);
                uint32_t f0[2] = { vh_[0], vh_[2] }, f1[2] = { vh_[1], vh_[3] };
                mma_f16(oacc[dt2 * 2 + 0], ph[ks], f0);
                mma_f16(oacc[dt2 * 2 + 1], ph[ks], f1);
            }
        __syncthreads();
    }

    lsum0 += __shfl_xor_sync(0xffffffffu, lsum0, 1);
    lsum0 += __shfl_xor_sync(0xffffffffu, lsum0, 2);
    lsum1 += __shfl_xor_sync(0xffffffffu, lsum1, 1);
    lsum1 += __shfl_xor_sync(0xffffffffu, lsum1, 2);
    float inv0 = 1.f / lsum0, inv1 = 1.f / lsum1;

    const int col0 = h * 64 + (lane & 3) * 2;
    size_t row0 = (size_t)b * SEQ + qr0;
#pragma unroll
    for (int dt = 0; dt < 8; dt++) {
#pragma unroll
        for (int hf = 0; hf < 2; hf++) {
            float v0 = oacc[dt][hf * 2 + 0] * (hf ? inv1 : inv0);
            float v1 = oacc[dt][hf * 2 + 1] * (hf ? inv1 : inv0);
            size_t idx = (row0 + hf * 8) * EMBED + col0 + dt * 8;
            __nv_bfloat16 h0 = __float2bfloat16(v0), h1 = __float2bfloat16(v1);
            *(__nv_bfloat162*)&g_ohi[idx] = __nv_bfloat162(h0, h1);
            *(__nv_bfloat162*)&g_olo[idx] = __nv_bfloat162(
                __float2bfloat16(v0 - __bfloat162float(h0)),
                __float2bfloat16(v1 - __bfloat162float(h1)));
        }
    }
}

// ---------------------------------------------------------------------------
extern "C" void kernel_launch(void* const* d_in, const int* in_sizes, int n_in,
                              void* d_out, int out_size)
{
    const float* x    = (const float*)d_in[0];
    const int*   mask = (const int*)  d_in[1];
    const float* Wq   = (const float*)d_in[2];
    const float* bq   = (const float*)d_in[3];
    const float* Wk   = (const float*)d_in[4];
    const float* bk   = (const float*)d_in[5];
    const float* Wv   = (const float*)d_in[6];
    const float* bv   = (const float*)d_in[7];
    const float* Wo   = (const float*)d_in[8];
    const float* bo   = (const float*)d_in[9];

    __nv_bfloat16 *xhi, *xlo, *ohi, *olo, *wthi, *wtlo;
    cudaGetSymbolAddress((void**)&xhi,  g_xhi);
    cudaGetSymbolAddress((void**)&xlo,  g_xlo);
    cudaGetSymbolAddress((void**)&ohi,  g_ohi);
    cudaGetSymbolAddress((void**)&olo,  g_olo);
    cudaGetSymbolAddress((void**)&wthi, g_wthi);
    cudaGetSymbolAddress((void**)&wtlo, g_wtlo);

    const size_t WSZ = (size_t)NDIM * KDIM;
    int n4x = MTOT * KDIM / 4;

    split_kernel<<<(n4x + 255) / 256, 256>>>(x, xhi, xlo, n4x);

    dim3 wg(NDIM / 32, KDIM / 32, 4);
    wsplit_kernel<<<wg, 256>>>(Wq, Wk, Wv, Wo, wthi, wtlo);

    pack_mask<<<2048, 256>>>(mask);

    cudaFuncSetAttribute(gemm_mma, cudaFuncAttributeMaxDynamicSharedMemorySize, GEMM_SMEM);
    dim3 gg(NDIM / 128, MTOT / 128);
    gemm_mma<<<gg, 128, GEMM_SMEM>>>(xhi, xlo, wthi + 0 * WSZ, wtlo + 0 * WSZ, bq, nullptr, 0);
    gemm_mma<<<gg, 128, GEMM_SMEM>>>(xhi, xlo, wthi + 1 * WSZ, wtlo + 1 * WSZ, bk, nullptr, 1);
    gemm_mma<<<gg, 128, GEMM_SMEM>>>(xhi, xlo, wthi + 2 * WSZ, wtlo + 2 * WSZ, bv, nullptr, 2);

    cudaFuncSetAttribute(attn_mma, cudaFuncAttributeMaxDynamicSharedMemorySize, ATT_SMEM);
    dim3 ga(SEQ / 128, NB * NHEADS);
    attn_mma<<<ga, 256, ATT_SMEM>>>();

    gemm_mma<<<gg, 128, GEMM_SMEM>>>(ohi, olo, wthi + 3 * WSZ, wtlo + 3 * WSZ, bo, (float*)d_out, 3);
}